// round 2
// baseline (speedup 1.0000x reference)
#include <cuda_runtime.h>

static constexpr int SEQ_LEN = 128;
static constexpr int BATCH   = 65536;
static constexpr int PAIRS   = BATCH / 2;   // 2 lanes per thread

struct Lane { float s, d; };

__device__ __forceinline__ void first_step(float rating, float w0, float w1,
                                           float w2, float w3, float w4, float w5,
                                           Lane& L)
{
    int ridx = (int)rating - 1;
    ridx = max(0, min(3, ridx));
    bool valid = (rating >= 1.0f) && (rating <= 4.0f);
    float s = (ridx == 0) ? w0 : (ridx == 1) ? w1 : (ridx == 2) ? w2 : w3;
    if (!valid) s = 1.0f;
    L.d = fminf(10.0f, fmaxf(1.0f, w4 - w5 * (rating - 3.0f)));
    L.s = fminf(36500.0f, fmaxf(0.01f, s));
}

__device__ __forceinline__ void step_lane(float t, float rt, Lane& L,
    float ew8, float w9, float w10l, float w11, float w12, float w13, float w14l,
    float w15, float w16, float w6, float c_d1, float c_d2)
{
    float s = L.s, d = L.d;

    // r = 9s / (9s + t);  omr = 1 - r
    float denom = fmaf(9.0f, s, t);
    float r     = __fdividef(9.0f * s, denom);
    float omr   = 1.0f - r;

    bool succ = (rt > 1.0f);

    // shared EX2: success needs exp((1-r)w10), failure exp((1-r)w14)
    float cexp = succ ? w10l : w14l;
    float E    = exp2f(omr * cexp);

    // shared pow: success s^(-w9), failure (s+1)^(w13)
    float base = succ ? s : (s + 1.0f);
    float kpow = succ ? -w9 : w13;
    float P    = exp2f(kpow * __log2f(base));

    // failure-only pow of d
    float pd   = exp2f(-w12 * __log2f(d));

    float ns;
    if (succ) {
        float hp  = (rt == 2.0f) ? w15 : 1.0f;
        float eb  = (rt == 4.0f) ? w16 : 1.0f;
        float fac = ew8 * (11.0f - d) * P * (E - 1.0f) * hp * eb;
        ns = fmaf(s, fac, s);
    } else {
        ns = fminf(w11 * pd * (P - 1.0f) * E, s);
    }

    float nd = fmaf(-w6, rt - 3.0f, d);
    nd = fmaf(c_d2, nd, c_d1);
    L.d = fminf(10.0f, fmaxf(1.0f, nd));
    L.s = fminf(36500.0f, fmaxf(0.01f, ns));
}

__global__ __launch_bounds__(256) void fsrs_kernel(
    const float4* __restrict__ in4,   // (SEQ_LEN, PAIRS) float4 = 2x(t, rating)
    const float*  __restrict__ w,     // (17,)
    float4*       __restrict__ out4,  // (SEQ_LEN, PAIRS) float4 = 2x(s, d) [+ final]
    long long out_elems)
{
    const int i = blockIdx.x * blockDim.x + threadIdx.x;
    if (i >= PAIRS) return;

    const float w0 = w[0],  w1 = w[1],  w2 = w[2],  w3 = w[3];
    const float w4 = w[4],  w5 = w[5],  w6 = w[6],  w7 = w[7];
    const float w8 = w[8],  w9 = w[9],  w10 = w[10], w11 = w[11];
    const float w12 = w[12], w13 = w[13], w14 = w[14], w15 = w[15], w16 = w[16];

    const float LOG2E = 1.4426950408889634f;
    const float ew8   = exp2f(w8 * LOG2E);
    const float w10l  = w10 * LOG2E;
    const float w14l  = w14 * LOG2E;
    const float c_d1  = w7 * w4;
    const float c_d2  = 1.0f - w7;

    Lane A, B;

    // ---- first step ----
    float4 x0 = __ldcs(&in4[i]);            // (t0, r0, t1, r1)
    first_step(x0.y, w0, w1, w2, w3, w4, w5, A);
    first_step(x0.w, w0, w1, w2, w3, w4, w5, B);
    __stcs(&out4[i], make_float4(A.s, A.d, B.s, B.d));

    // ---- scan over steps 1..127, one-ahead prefetch ----
    float4 xN = __ldcs(&in4[PAIRS + i]);
    #pragma unroll 4
    for (int n = 1; n < SEQ_LEN; ++n) {
        float4 x = xN;
        if (n + 1 < SEQ_LEN)
            xN = __ldcs(&in4[(n + 1) * PAIRS + i]);

        step_lane(x.x, x.y, A, ew8, w9, w10l, w11, w12, w13, w14l,
                  w15, w16, w6, c_d1, c_d2);
        step_lane(x.z, x.w, B, ew8, w9, w10l, w11, w12, w13, w14l,
                  w15, w16, w6, c_d1, c_d2);

        __stcs(&out4[n * PAIRS + i], make_float4(A.s, A.d, B.s, B.d));
    }

    // ---- final_state tensor, if present in the output buffer ----
    if (out_elems >= (long long)(SEQ_LEN + 1) * BATCH * 2) {
        __stcs(&out4[SEQ_LEN * PAIRS + i], make_float4(A.s, A.d, B.s, B.d));
    }
}

extern "C" void kernel_launch(void* const* d_in, const int* in_sizes, int n_in,
                              void* d_out, int out_size)
{
    const float4* inputs = (const float4*)d_in[0];  // (128, 65536, 2) f32
    const float*  w      = (const float*)d_in[1];   // (17,) f32
    float4* out          = (float4*)d_out;

    dim3 block(256);
    dim3 grid(PAIRS / 256);                          // 128 blocks
    fsrs_kernel<<<grid, block>>>(inputs, w, out, (long long)out_size);
}

// round 3
// speedup vs baseline: 1.0504x; 1.0504x over previous
#include <cuda_runtime.h>

static constexpr int SEQ_LEN = 128;
static constexpr int BATCH   = 65536;

__global__ __launch_bounds__(64) void fsrs_kernel(
    const float2* __restrict__ in2,   // (SEQ_LEN, BATCH) of (t, rating)
    const float*  __restrict__ w,     // (17,)
    float2*       __restrict__ out2,  // (SEQ_LEN, BATCH) of (s, d) [+ final (BATCH)]
    long long out_elems)
{
    const int b = blockIdx.x * blockDim.x + threadIdx.x;
    if (b >= BATCH) return;

    const float w0 = w[0],  w1 = w[1],  w2 = w[2],  w3 = w[3];
    const float w4 = w[4],  w5 = w[5],  w6 = w[6],  w7 = w[7];
    const float w8 = w[8],  w9 = w[9],  w10 = w[10], w11 = w[11];
    const float w12 = w[12], w13 = w[13], w14 = w[14], w15 = w[15], w16 = w[16];

    const float LOG2E = 1.4426950408889634f;
    const float ew8   = exp2f(w8 * LOG2E);   // exp(w8), loop-invariant
    const float w10l  = w10 * LOG2E;
    const float w14l  = w14 * LOG2E;
    const float c_d1  = w7 * w4;
    const float c_d2  = 1.0f - w7;

    // ---- first step ----
    float2 x0 = in2[b];
    {
        float rating0 = x0.y;
        int ridx = (int)rating0 - 1;
        ridx = max(0, min(3, ridx));
        bool valid = (rating0 >= 1.0f) && (rating0 <= 4.0f);
        float s0 = (ridx == 0) ? w0 : (ridx == 1) ? w1 : (ridx == 2) ? w2 : w3;
        if (!valid) s0 = 1.0f;
        float d0 = fminf(10.0f, fmaxf(1.0f, w4 - w5 * (rating0 - 3.0f)));
        s0 = fminf(36500.0f, fmaxf(0.01f, s0));
        out2[b] = make_float2(s0, d0);

        float s = s0, d = d0;

        // ---- scan over steps 1..127, one-ahead prefetch ----
        float2 xN = in2[BATCH + b];
        #pragma unroll 4
        for (int n = 1; n < SEQ_LEN; ++n) {
            float t  = xN.x;
            float rt = xN.y;
            if (n + 1 < SEQ_LEN)
                xN = in2[(n + 1) * BATCH + b];

            bool succ = (rt > 1.0f);

            // omr = 1 - r = t / (9s + t)
            float denom = fmaf(9.0f, s, t);
            float omr   = __fdividef(t, denom);

            // shared EX2: exp((1-r)*w10) on success, exp((1-r)*w14) on failure
            float cexp = succ ? w10l : w14l;
            float E    = exp2f(omr * cexp);

            // shared pow: s^(-w9) on success, (s+1)^(w13) on failure
            float base = succ ? s : (s + 1.0f);
            float kpow = succ ? -w9 : w13;
            float P    = exp2f(kpow * __log2f(base));

            float ns;
            if (succ) {
                float hp  = (rt == 2.0f) ? w15 : 1.0f;
                float eb  = (rt == 4.0f) ? w16 : 1.0f;
                float fac = ew8 * (11.0f - d) * P * (E - 1.0f) * hp * eb;
                ns = fmaf(s, fac, s);
            } else {
                float pd = exp2f(-w12 * __log2f(d));   // d^(-w12)
                ns = fminf(w11 * pd * (P - 1.0f) * E, s);
            }

            float nd = fmaf(-w6, rt - 3.0f, d);        // d - w6*(rt-3)
            nd = fmaf(c_d2, nd, c_d1);                 // w7*w4 + (1-w7)*nd
            d  = fminf(10.0f, fmaxf(1.0f, nd));
            s  = fminf(36500.0f, fmaxf(0.01f, ns));

            out2[n * BATCH + b] = make_float2(s, d);
        }

        // ---- final_state tensor, if present in the output buffer ----
        if (out_elems >= (long long)(SEQ_LEN + 1) * BATCH * 2) {
            out2[SEQ_LEN * BATCH + b] = make_float2(s, d);
        }
    }
}

extern "C" void kernel_launch(void* const* d_in, const int* in_sizes, int n_in,
                              void* d_out, int out_size)
{
    const float2* inputs = (const float2*)d_in[0];  // (128, 65536, 2) f32
    const float*  w      = (const float*)d_in[1];   // (17,) f32
    float2* out          = (float2*)d_out;

    dim3 block(64);
    dim3 grid(BATCH / 64);                           // 1024 blocks
    fsrs_kernel<<<grid, block>>>(inputs, w, out, (long long)out_size);
}

// round 4
// speedup vs baseline: 1.2169x; 1.1586x over previous
#include <cuda_runtime.h>

static constexpr int SEQ_LEN = 128;
static constexpr int BATCH   = 65536;

__global__ __launch_bounds__(128) void fsrs_kernel(
    const float2* __restrict__ in2,   // (SEQ_LEN, BATCH) of (t, rating)
    const float*  __restrict__ w,     // (17,)
    float2*       __restrict__ out2,  // (SEQ_LEN, BATCH) of (s, d) [+ final (BATCH)]
    long long out_elems)
{
    const int b = blockIdx.x * blockDim.x + threadIdx.x;
    if (b >= BATCH) return;

    const float w0 = w[0],  w1 = w[1],  w2 = w[2],  w3 = w[3];
    const float w4 = w[4],  w5 = w[5],  w6 = w[6],  w7 = w[7];
    const float w8 = w[8],  w9 = w[9],  w10 = w[10], w11 = w[11];
    const float w12 = w[12], w13 = w[13], w14 = w[14], w15 = w[15], w16 = w[16];

    const float LOG2E = 1.4426950408889634f;
    const float ew8   = exp2f(w8 * LOG2E);   // exp(w8), loop-invariant
    const float w10l  = w10 * LOG2E;
    const float w14l  = w14 * LOG2E;
    const float c_d1  = w7 * w4;
    const float c_d2  = 1.0f - w7;

    // ---- first step ----
    float2 x0 = in2[b];
    float rating0 = x0.y;
    int ridx = (int)rating0 - 1;
    ridx = max(0, min(3, ridx));
    bool valid = (rating0 >= 1.0f) && (rating0 <= 4.0f);
    float s = (ridx == 0) ? w0 : (ridx == 1) ? w1 : (ridx == 2) ? w2 : w3;
    if (!valid) s = 1.0f;
    float d = fminf(10.0f, fmaxf(1.0f, w4 - w5 * (rating0 - 3.0f)));
    s = fminf(36500.0f, fmaxf(0.01f, s));
    out2[b] = make_float2(s, d);

    // ---- scan over steps 1..127, one-ahead prefetch, fully branchless body ----
    float2 xN = in2[BATCH + b];
    #pragma unroll 4
    for (int n = 1; n < SEQ_LEN; ++n) {
        float t  = xN.x;
        float rt = xN.y;
        if (n + 1 < SEQ_LEN)
            xN = in2[(n + 1) * BATCH + b];

        bool succ = (rt > 1.0f);

        // omr = 1 - r = t / (9s + t)
        float denom = fmaf(9.0f, s, t);
        float omr   = __fdividef(t, denom);

        // shared EX2: exp((1-r)*w10) on success, exp((1-r)*w14) on failure
        float cexp = succ ? w10l : w14l;
        float E    = exp2f(omr * cexp);

        // shared pow: s^(-w9) on success, (s+1)^(w13) on failure
        float base = succ ? s : (s + 1.0f);
        float kpow = succ ? -w9 : w13;
        float P    = exp2f(kpow * __log2f(base));

        // failure-only pow of d — computed unconditionally (no divergence)
        float pd   = exp2f(-w12 * __log2f(d));

        // success result
        float hp  = (rt == 2.0f) ? w15 : 1.0f;
        float eb  = (rt == 4.0f) ? w16 : 1.0f;
        float fac = ew8 * (11.0f - d) * P * (E - 1.0f) * hp * eb;
        float ns_succ = fmaf(s, fac, s);

        // failure result
        float ns_fail = fminf(w11 * pd * (P - 1.0f) * E, s);

        float ns = succ ? ns_succ : ns_fail;

        float nd = fmaf(-w6, rt - 3.0f, d);        // d - w6*(rt-3)
        nd = fmaf(c_d2, nd, c_d1);                 // w7*w4 + (1-w7)*nd
        d  = fminf(10.0f, fmaxf(1.0f, nd));
        s  = fminf(36500.0f, fmaxf(0.01f, ns));

        out2[n * BATCH + b] = make_float2(s, d);
    }

    // ---- final_state tensor, if present in the output buffer ----
    if (out_elems >= (long long)(SEQ_LEN + 1) * BATCH * 2) {
        out2[SEQ_LEN * BATCH + b] = make_float2(s, d);
    }
}

extern "C" void kernel_launch(void* const* d_in, const int* in_sizes, int n_in,
                              void* d_out, int out_size)
{
    const float2* inputs = (const float2*)d_in[0];  // (128, 65536, 2) f32
    const float*  w      = (const float*)d_in[1];   // (17,) f32
    float2* out          = (float2*)d_out;

    dim3 block(128);
    dim3 grid(BATCH / 128);                          // 512 blocks
    fsrs_kernel<<<grid, block>>>(inputs, w, out, (long long)out_size);
}

// round 5
// speedup vs baseline: 1.5984x; 1.3134x over previous
#include <cuda_runtime.h>

static constexpr int SEQ_LEN = 128;
static constexpr int BATCH   = 65536;

__global__ __launch_bounds__(128) void fsrs_kernel(
    const float2* __restrict__ in2,   // (SEQ_LEN, BATCH) of (t, rating)
    const float*  __restrict__ w,     // (17,)
    float2*       __restrict__ out2,  // (SEQ_LEN, BATCH) of (s, d) [+ final (BATCH)]
    long long out_elems)
{
    const int b = blockIdx.x * blockDim.x + threadIdx.x;
    if (b >= BATCH) return;

    const float w0 = w[0],  w1 = w[1],  w2 = w[2],  w3 = w[3];
    const float w4 = w[4],  w5 = w[5],  w6 = w[6],  w7 = w[7];
    const float w8 = w[8],  w9 = w[9],  w10 = w[10], w11 = w[11];
    const float w12 = w[12], w13 = w[13], w14 = w[14], w15 = w[15], w16 = w[16];

    const float LOG2E = 1.4426950408889634f;
    const float ew8   = exp2f(w8 * LOG2E);   // exp(w8), loop-invariant
    const float w10l  = w10 * LOG2E;
    const float w14l  = w14 * LOG2E;
    const float c_d1  = w7 * w4;
    const float c_d2  = 1.0f - w7;

    // ---- first step ----
    float2 x0 = in2[b];
    float rating0 = x0.y;
    int ridx = (int)rating0 - 1;
    ridx = max(0, min(3, ridx));
    bool valid = (rating0 >= 1.0f) && (rating0 <= 4.0f);
    float s = (ridx == 0) ? w0 : (ridx == 1) ? w1 : (ridx == 2) ? w2 : w3;
    if (!valid) s = 1.0f;
    float d = fminf(10.0f, fmaxf(1.0f, w4 - w5 * (rating0 - 3.0f)));
    s = fminf(36500.0f, fmaxf(0.01f, s));
    out2[b] = make_float2(s, d);

    // ---- scan over steps 1..127 ----
    // Plain indexed loads at the top of the body: state-independent, so under
    // unroll 4 ptxas front-batches them (MLP≈4) and hides DRAM latency.
    #pragma unroll 4
    for (int n = 1; n < SEQ_LEN; ++n) {
        float2 x = in2[n * BATCH + b];
        float t  = x.x;
        float rt = x.y;

        bool succ = (rt > 1.0f);

        // omr = 1 - r = t / (9s + t)
        float denom = fmaf(9.0f, s, t);
        float omr   = __fdividef(t, denom);

        // shared EX2: exp((1-r)*w10) on success, exp((1-r)*w14) on failure
        float cexp = succ ? w10l : w14l;
        float E    = exp2f(omr * cexp);

        // shared pow: s^(-w9) on success, (s+1)^(w13) on failure
        float base = succ ? s : (s + 1.0f);
        float kpow = succ ? -w9 : w13;
        float P    = exp2f(kpow * __log2f(base));

        // failure-only pow of d — unconditional, off the s-critical path
        float pd   = exp2f(-w12 * __log2f(d));

        // off-chain constants join the E-path last (explicit association)
        float hp  = (rt == 2.0f) ? w15 : 1.0f;
        float eb  = (rt == 4.0f) ? w16 : 1.0f;
        float C   = (ew8 * (11.0f - d)) * (hp * eb);   // ready before E
        float CP  = C * P;

        float ns_succ = fmaf(s, CP * (E - 1.0f), s);
        float ns_fail = fminf((w11 * pd) * ((P - 1.0f) * E), s);
        float ns = succ ? ns_succ : ns_fail;

        float nd = fmaf(-w6, rt - 3.0f, d);        // d - w6*(rt-3)
        nd = fmaf(c_d2, nd, c_d1);                 // w7*w4 + (1-w7)*nd
        d  = fminf(10.0f, fmaxf(1.0f, nd));
        s  = fminf(36500.0f, fmaxf(0.01f, ns));

        out2[n * BATCH + b] = make_float2(s, d);
    }

    // ---- final_state tensor, if present in the output buffer ----
    if (out_elems >= (long long)(SEQ_LEN + 1) * BATCH * 2) {
        out2[SEQ_LEN * BATCH + b] = make_float2(s, d);
    }
}

extern "C" void kernel_launch(void* const* d_in, const int* in_sizes, int n_in,
                              void* d_out, int out_size)
{
    const float2* inputs = (const float2*)d_in[0];  // (128, 65536, 2) f32
    const float*  w      = (const float*)d_in[1];   // (17,) f32
    float2* out          = (float2*)d_out;

    dim3 block(128);
    dim3 grid(BATCH / 128);                          // 512 blocks
    fsrs_kernel<<<grid, block>>>(inputs, w, out, (long long)out_size);
}